// round 14
// baseline (speedup 1.0000x reference)
#include <cuda_runtime.h>
#include <cuda_fp16.h>
#include <cstdint>
#include <math.h>

#define BATCH 8
#define NTOK  1024
#define KVD   960
#define NH    4
#define HKV   (NH * KVD)   // 3840
#define CT    960          // sum of branch channels 64+128+256+512

typedef long long ll;

#define BR_C(br)   (64 << (br))
#define BR_P(br)   ((64 << (br)) - 64)

// ---------------- scratch (static __device__ — no allocations allowed) ----------------
static __device__ __half g_G  [(size_t)BATCH * CT * KVD];
static __device__ __half g_T  [(size_t)BATCH * NH * CT * KVD];
static __device__ float  g_S  [(size_t)BATCH * CT * HKV];      // fp32 scores
static __device__ __half g_S16[(size_t)BATCH * CT * HKV];      // fp16 probs
static __device__ __half g_U  [(size_t)BATCH * NH * CT * KVD]; // per-head U partials
static __device__ __half g_CX [(size_t)BATCH * CT * NTOK];
static __device__ float  g_part[2048 * 2];

// ---------------- fp16 helpers ----------------
__device__ __forceinline__ uint32_t h2pack(float lo, float hi) {
    uint32_t r;
    asm("cvt.rn.f16x2.f32 %0, %1, %2;" : "=r"(r) : "f"(hi), "f"(lo));
    return r;
}
__device__ __forceinline__ uint32_t packh(__half lo, __half hi) {
    __half2 h = __halves2half2(lo, hi);
    return *(uint32_t*)&h;
}

__device__ __forceinline__ void mma16816(float* c, const uint4& a, const uint2& b) {
    asm volatile(
        "mma.sync.aligned.m16n8k16.row.col.f32.f16.f16.f32 "
        "{%0,%1,%2,%3}, {%4,%5,%6,%7}, {%8,%9}, {%0,%1,%2,%3};"
        : "+f"(c[0]), "+f"(c[1]), "+f"(c[2]), "+f"(c[3])
        : "r"(a.x), "r"(a.y), "r"(a.z), "r"(a.w), "r"(b.x), "r"(b.y));
}

// ======================= fp32 producers =======================
template <bool T>
__device__ __forceinline__ void ldgA(const float* __restrict__ A, int lda, int tileM,
                                     int M, int kt, int t, float4* q)
{
    const int b = t >> 4, kb = b >> 3, mb = b & 7;
    const int m0 = tileM + mb * 16 + ((t & 15) >> 1);
    const int k0 = kt + kb * 16 + (t & 1) * 4;
    const bool v0 = m0 < M, v1 = (m0 + 8) < M;
    if (!T) {
        const float4 Z = make_float4(0.f, 0.f, 0.f, 0.f);
        q[0] = v0 ? *(const float4*)(A + (ll)m0 * lda + k0)           : Z;
        q[1] = v0 ? *(const float4*)(A + (ll)m0 * lda + k0 + 8)       : Z;
        q[2] = v1 ? *(const float4*)(A + (ll)(m0 + 8) * lda + k0)     : Z;
        q[3] = v1 ? *(const float4*)(A + (ll)(m0 + 8) * lda + k0 + 8) : Z;
    } else {
        float* f = (float*)q;
#pragma unroll
        for (int run = 0; run < 2; run++)
#pragma unroll
            for (int i = 0; i < 4; i++) {
                const ll ko = (ll)(k0 + run * 8 + i) * lda;
                f[run * 4 + i]     = v0 ? A[ko + m0]     : 0.f;
                f[8 + run * 4 + i] = v1 ? A[ko + m0 + 8] : 0.f;
            }
    }
}

__device__ __forceinline__ void stsA(uint4* sA, int t, const float4* q)
{
    uint4 v0, v1;
    v0.x = h2pack(q[0].x, q[0].y); v0.y = h2pack(q[2].x, q[2].y);
    v0.z = h2pack(q[1].x, q[1].y); v0.w = h2pack(q[3].x, q[3].y);
    v1.x = h2pack(q[0].z, q[0].w); v1.y = h2pack(q[2].z, q[2].w);
    v1.z = h2pack(q[1].z, q[1].w); v1.w = h2pack(q[3].z, q[3].w);
    const int b = t >> 4;
    const int l0 = (t & 15) * 2, l1 = l0 + 1;
    sA[b * 32 + (l0 ^ ((l0 >> 3) & 1))] = v0;
    sA[b * 32 + (l1 ^ ((l1 >> 3) & 1))] = v1;
}

template <bool T>
__device__ __forceinline__ void ldgB(const float* __restrict__ B, int ldb, int tileN,
                                     int N, int kt, int t, float4* q)
{
    const int b = t >> 3, kb = b >> 4, nb = b & 15;
    const int n = tileN + nb * 8 + (t & 7);
    const int k0 = kt + kb * 16;
    const bool v = n < N;
    if (!T) {
        const float4 Z = make_float4(0.f, 0.f, 0.f, 0.f);
        const float4* p = (const float4*)(B + (ll)n * ldb + k0);
        q[0] = v ? p[0] : Z; q[1] = v ? p[1] : Z;
        q[2] = v ? p[2] : Z; q[3] = v ? p[3] : Z;
    } else {
        float* f = (float*)q;
#pragma unroll
        for (int i = 0; i < 16; i++)
            f[i] = v ? B[(ll)(k0 + i) * ldb + n] : 0.f;
    }
}

__device__ __forceinline__ void stsB(uint4* sB, int t, const float4* q)
{
    uint4 v0, v1;
    v0.x = h2pack(q[0].x, q[0].y); v0.y = h2pack(q[2].x, q[2].y);
    v0.z = h2pack(q[0].z, q[0].w); v0.w = h2pack(q[2].z, q[2].w);
    v1.x = h2pack(q[1].x, q[1].y); v1.y = h2pack(q[3].x, q[3].y);
    v1.z = h2pack(q[1].z, q[1].w); v1.w = h2pack(q[3].z, q[3].w);
    const int b = t >> 3;
    const int u0 = (t & 7) * 2, u1 = u0 + 1;
    sB[b * 16 + (u0 ^ ((u0 >> 3) & 1))] = v0;
    sB[b * 16 + (u1 ^ ((u1 >> 3) & 1))] = v1;
}

// ======================= fp16 producers (pure repack) =======================
__device__ __forceinline__ void ldgA16(const __half* __restrict__ A, int lda, int tileM,
                                       int M, int kt, int t, uint2* w)
{
    const int b = t >> 4, kb = b >> 3, mb = b & 7;
    const int m0 = tileM + mb * 16 + ((t & 15) >> 1);
    const int k0 = kt + kb * 16 + (t & 1) * 4;
    const bool v0 = m0 < M, v1 = (m0 + 8) < M;
    const uint2 Z = make_uint2(0u, 0u);
    w[0] = v0 ? *(const uint2*)(A + (ll)m0 * lda + k0)           : Z;
    w[1] = v0 ? *(const uint2*)(A + (ll)m0 * lda + k0 + 8)       : Z;
    w[2] = v1 ? *(const uint2*)(A + (ll)(m0 + 8) * lda + k0)     : Z;
    w[3] = v1 ? *(const uint2*)(A + (ll)(m0 + 8) * lda + k0 + 8) : Z;
}

// A = sum of 4 head-slabs (each hs elements apart), fp16 row-major
__device__ __forceinline__ void ldgA16s4(const __half* __restrict__ A, int lda, ll hs,
                                         int tileM, int M, int kt, int t, uint2* w)
{
    const int b = t >> 4, kb = b >> 3, mb = b & 7;
    const int m0 = tileM + mb * 16 + ((t & 15) >> 1);
    const int k0 = kt + kb * 16 + (t & 1) * 4;
    const bool v0 = m0 < M, v1 = (m0 + 8) < M;
    const uint2 Z = make_uint2(0u, 0u);
    const ll o0 = (ll)m0 * lda + k0;
    const ll o1 = (ll)(m0 + 8) * lda + k0;
    __half2 s[8];
#pragma unroll
    for (int i = 0; i < 8; i++) s[i] = __halves2half2(__float2half(0.f), __float2half(0.f));
#pragma unroll
    for (int h = 0; h < NH; h++) {
        const __half* Ah = A + (ll)h * hs;
        uint2 a0 = v0 ? *(const uint2*)(Ah + o0)     : Z;
        uint2 a1 = v0 ? *(const uint2*)(Ah + o0 + 8) : Z;
        uint2 a2 = v1 ? *(const uint2*)(Ah + o1)     : Z;
        uint2 a3 = v1 ? *(const uint2*)(Ah + o1 + 8) : Z;
        s[0] = __hadd2(s[0], *(__half2*)&a0.x); s[1] = __hadd2(s[1], *(__half2*)&a0.y);
        s[2] = __hadd2(s[2], *(__half2*)&a1.x); s[3] = __hadd2(s[3], *(__half2*)&a1.y);
        s[4] = __hadd2(s[4], *(__half2*)&a2.x); s[5] = __hadd2(s[5], *(__half2*)&a2.y);
        s[6] = __hadd2(s[6], *(__half2*)&a3.x); s[7] = __hadd2(s[7], *(__half2*)&a3.y);
    }
    w[0] = make_uint2(*(uint32_t*)&s[0], *(uint32_t*)&s[1]);
    w[1] = make_uint2(*(uint32_t*)&s[2], *(uint32_t*)&s[3]);
    w[2] = make_uint2(*(uint32_t*)&s[4], *(uint32_t*)&s[5]);
    w[3] = make_uint2(*(uint32_t*)&s[6], *(uint32_t*)&s[7]);
}

__device__ __forceinline__ void ldgA16T(const __half* __restrict__ A, int lda, int tileM,
                                        int M, int kt, int t, uint2* w)
{
    const int b = t >> 4, kb = b >> 3, mb = b & 7;
    const int m0 = tileM + mb * 16 + ((t & 15) >> 1);
    const int k0 = kt + kb * 16 + (t & 1) * 4;
    const bool v0 = m0 < M, v1 = (m0 + 8) < M;
    const __half Z = __float2half(0.f);
    __half h0[8], h1[8];
#pragma unroll
    for (int run = 0; run < 2; run++)
#pragma unroll
        for (int i = 0; i < 4; i++) {
            const ll ko = (ll)(k0 + run * 8 + i) * lda;
            h0[run * 4 + i] = v0 ? A[ko + m0]     : Z;
            h1[run * 4 + i] = v1 ? A[ko + m0 + 8] : Z;
        }
    w[0] = make_uint2(packh(h0[0], h0[1]), packh(h0[2], h0[3]));
    w[1] = make_uint2(packh(h0[4], h0[5]), packh(h0[6], h0[7]));
    w[2] = make_uint2(packh(h1[0], h1[1]), packh(h1[2], h1[3]));
    w[3] = make_uint2(packh(h1[4], h1[5]), packh(h1[6], h1[7]));
}

__device__ __forceinline__ void stsA16(uint4* sA, int t, const uint2* w)
{
    uint4 v0, v1;
    v0.x = w[0].x; v0.y = w[2].x; v0.z = w[1].x; v0.w = w[3].x;
    v1.x = w[0].y; v1.y = w[2].y; v1.z = w[1].y; v1.w = w[3].y;
    const int b = t >> 4;
    const int l0 = (t & 15) * 2, l1 = l0 + 1;
    sA[b * 32 + (l0 ^ ((l0 >> 3) & 1))] = v0;
    sA[b * 32 + (l1 ^ ((l1 >> 3) & 1))] = v1;
}

__device__ __forceinline__ void ldgB16T(const __half* __restrict__ B, int ldb, int tileN,
                                        int N, int kt, int t, uint4& v0, uint4& v1)
{
    const int b = t >> 3, kb = b >> 4, nb = b & 15;
    const int n = tileN + nb * 8 + (t & 7);
    const int k0 = kt + kb * 16;
    const bool v = n < N;
    const __half Z = __float2half(0.f);
    __half f[16];
#pragma unroll
    for (int i = 0; i < 16; i++)
        f[i] = v ? B[(ll)(k0 + i) * ldb + n] : Z;
    v0.x = packh(f[0],  f[1]);  v0.y = packh(f[8],  f[9]);
    v0.z = packh(f[2],  f[3]);  v0.w = packh(f[10], f[11]);
    v1.x = packh(f[4],  f[5]);  v1.y = packh(f[12], f[13]);
    v1.z = packh(f[6],  f[7]);  v1.w = packh(f[14], f[15]);
}

__device__ __forceinline__ void stsB16(uint4* sB, int t, const uint4& v0, const uint4& v1)
{
    const int b = t >> 3;
    const int u0 = (t & 7) * 2, u1 = u0 + 1;
    sB[b * 16 + (u0 ^ ((u0 >> 3) & 1))] = v0;
    sB[b * 16 + (u1 ^ ((u1 >> 3) & 1))] = v1;
}

// ======================= merged-stage GEMM descriptors =======================
struct GemmDesc {
    const float* A;
    const float* B;
    float*       C;
    int M, N, K, lda, ldb, ldc;
    int aDiv, bDiv, cDiv;
    ll aS1, aS2, bS1, bS2, cS1, cS2;
    float alpha;
    int xB, yB;
    int off;
};
struct Desc4 { GemmDesc d[4]; float* part; };

// ---------------- config-templated compute path ----------------
template <int JMAX>
__device__ __forceinline__ void compute_T(const uint4* __restrict__ ap,
                                          const uint2* __restrict__ bp,
                                          float acc[2][8][4],
                                          int wmSel, int nbBase, int la, int lb2)
{
#pragma unroll
    for (int s = 0; s < 2; s++) {
        uint4 av[2];
#pragma unroll
        for (int i = 0; i < 2; i++)
            av[i] = ap[(s * 8 + wmSel * 2 + i) * 32 + la];
        uint2 bv[JMAX];
#pragma unroll
        for (int j = 0; j < JMAX; j++)
            bv[j] = bp[(s * 16 + nbBase + j) * 32 + lb2];
#pragma unroll
        for (int i = 0; i < 2; i++)
#pragma unroll
            for (int j = 0; j < JMAX; j++)
                mma16816(acc[i][j], av[i], bv[j]);
    }
}

// ======================= fp16 tensor-core merged batched GEMM =======================
// Runtime half-tile modes: mHalf (M==64) and nHalf (N - tileN <= 64) skip padded HMMAs.
// A4: A operand = sum of 4 fp16 head slabs (stride M*lda), row-major.
template <bool TA, bool TB, bool STATS, bool AH, bool BH, bool CH, bool A4>
__global__ __launch_bounds__(256, 2)
void tgemm_m(Desc4 ds)
{
    __shared__ uint4 sA[2][512];
    __shared__ uint4 sB[2][512];

    const int bid = blockIdx.x;
    int br = 0;
    if (bid >= ds.d[1].off) br = 1;
    if (bid >= ds.d[2].off) br = 2;
    if (bid >= ds.d[3].off) br = 3;
    const GemmDesc& g = ds.d[br];

    const int local = bid - g.off;
    const int x  = local % g.xB;
    const int t2 = local / g.xB;
    const int y  = t2 % g.yB;
    const int z  = t2 / g.yB;

    const ll aOff = (ll)(z / g.aDiv) * g.aS1 + (ll)(z % g.aDiv) * g.aS2;
    const ll bOff = (ll)(z / g.bDiv) * g.bS1 + (ll)(z % g.bDiv) * g.bS2;
    const ll cOff = (ll)(z / g.cDiv) * g.cS1 + (ll)(z % g.cDiv) * g.cS2;
    const float*  A   = g.A + aOff;
    const __half* A16 = (const __half*)g.A + aOff;
    const float*  B   = g.B + bOff;
    const __half* B16 = (const __half*)g.B + bOff;
    float*        C   = g.C + cOff;
    __half*       C16 = (__half*)g.C + cOff;
    const int M = g.M, N = g.N, K = g.K;
    const int lda = g.lda, ldb = g.ldb, ldc = g.ldc;
    const float alpha = g.alpha;

    const int tid  = threadIdx.x;
    const int lane = tid & 31;
    const int wid  = tid >> 5;
    const int tileM = y * 128;
    const int tileN = x * 128;

    const bool mHalf = (M == 64);
    const bool nHalf = (N - tileN) <= 64;
    const int wmSel = mHalf ? (wid >> 2) : (wid >> 1);
    const int wnSel = mHalf ? (wid & 3)  : (wid & 1);
    const int nbBase = (mHalf ? wnSel * 4 : wnSel * 8) >> (nHalf ? 1 : 0);
    const int jmax = (mHalf ? 4 : 8) >> (nHalf ? 1 : 0);
    const int cfg = (mHalf ? 2 : 0) | (nHalf ? 1 : 0);

    float acc[2][8][4];
#pragma unroll
    for (int i = 0; i < 2; i++)
#pragma unroll
        for (int j = 0; j < 8; j++)
#pragma unroll
            for (int t = 0; t < 4; t++) acc[i][j][t] = 0.f;

    const int la  = lane ^ ((lane >> 3) & 1);
    const int lb2 = (((lane >> 1) ^ ((lane >> 4) & 1)) << 1) | (lane & 1);

    auto compute = [&](int buf) {
        const uint4* ap = sA[buf];
        const uint2* bp = (const uint2*)sB[buf];
        switch (cfg) {
            case 0: compute_T<8>(ap, bp, acc, wmSel, nbBase, la, lb2); break;
            case 1: compute_T<4>(ap, bp, acc, wmSel, nbBase, la, lb2); break;
            case 2: compute_T<4>(ap, bp, acc, wmSel, nbBase, la, lb2); break;
            default: compute_T<2>(ap, bp, acc, wmSel, nbBase, la, lb2); break;
        }
    };

    const int nk = K >> 5;
    float4 qa[4], qb[4];
    uint2  wa[4];
    uint4  wb0, wb1;

    auto produceA = [&](int kt) {
        if (A4)      ldgA16s4(A16, lda, (ll)M * lda, tileM, M, kt, tid, wa);
        else if (AH) { if (TA) ldgA16T(A16, lda, tileM, M, kt, tid, wa);
                       else    ldgA16 (A16, lda, tileM, M, kt, tid, wa); }
        else          ldgA<TA>(A, lda, tileM, M, kt, tid, qa);
    };
    auto produceB = [&](int kt) {
        if (BH) ldgB16T(B16, ldb, tileN, N, kt, tid, wb0, wb1);
        else    ldgB<TB>(B, ldb, tileN, N, kt, tid, qb);
    };
    auto storeAB = [&](int buf) {
        if (AH || A4) stsA16(sA[buf], tid, wa); else stsA(sA[buf], tid, qa);
        if (BH) stsB16(sB[buf], tid, wb0, wb1); else stsB(sB[buf], tid, qb);
    };

    produceA(0);
    produceB(0);
    storeAB(0);
    __syncthreads();

    int buf = 0;
    for (int it = 1; it < nk; it++) {
        produceA(it * 32);
        produceB(it * 32);
        compute(buf);
        storeAB(buf ^ 1);
        __syncthreads();
        buf ^= 1;
    }
    compute(buf);

    if (STATS) {
        float s = 0.f, s2 = 0.f;
#pragma unroll
        for (int i = 0; i < 2; i++)
            for (int j = 0; j < jmax; j++)
#pragma unroll
                for (int t = 0; t < 4; t++) {
                    const float v = acc[i][j][t] * alpha;
                    s += v; s2 += v * v;
                }
        __syncthreads();
        float* sa = (float*)&sA[0][0];
        float* sb = sa + 256;
        sa[tid] = s; sb[tid] = s2;
        __syncthreads();
        for (int off = 128; off > 0; off >>= 1) {
            if (tid < off) { sa[tid] += sa[tid + off]; sb[tid] += sb[tid + off]; }
            __syncthreads();
        }
        if (tid == 0) {
            ds.part[bid * 2 + 0] = sa[0];
            ds.part[bid * 2 + 1] = sb[0];
        }
    }

    // epilogue (generalized over configs)
    for (int i = 0; i < 2; i++) {
        for (int j = 0; j < jmax; j++) {
            const int row = tileM + wmSel * 32 + i * 16 + (lane >> 2);
            const int col = tileN + nbBase * 8 + j * 8 + ((lane & 3) << 1);
            if (col < N) {
                if (CH) {
                    if (row < M)
                        *(uint32_t*)&C16[(ll)row * ldc + col] =
                            h2pack(acc[i][j][0] * alpha, acc[i][j][1] * alpha);
                    if (row + 8 < M)
                        *(uint32_t*)&C16[(ll)(row + 8) * ldc + col] =
                            h2pack(acc[i][j][2] * alpha, acc[i][j][3] * alpha);
                } else {
                    if (row < M) {
                        float2 v = make_float2(acc[i][j][0] * alpha, acc[i][j][1] * alpha);
                        *(float2*)&C[(ll)row * ldc + col] = v;
                    }
                    if (row + 8 < M) {
                        float2 v = make_float2(acc[i][j][2] * alpha, acc[i][j][3] * alpha);
                        *(float2*)&C[(ll)(row + 8) * ldc + col] = v;
                    }
                }
            }
        }
    }
}

// ---------------- fused stats-fold + norm + softmax: fp32 scores -> fp16 probs ------------
// dS fill order is br3,br2,br1,br0: per-branch partial offsets {br0:1792, br1:1536, br2:1024, br3:0}
__global__ __launch_bounds__(256) void norm_softmax_m(
    const float* __restrict__ S, __half* __restrict__ S16,
    const float* __restrict__ part)
{
    const int gid = blockIdx.x;
    int br = 0;
    if (gid >= 2048)  br = 1;
    if (gid >= 6144)  br = 2;
    if (gid >= 14336) br = 3;
    const int off = (2048 << br) - 2048;
    const int local = gid - off;
    const int C = BR_C(br);

    const int h = local % NH;
    const int bc = local / NH;
    const int c = bc % C;
    const int b = bc / C;
    const int tid  = threadIdx.x;
    const int lane = tid & 31;
    const int wid  = tid >> 5;

    const ll eoff = (ll)BATCH * BR_P(br) * HKV + ((ll)b * C + c) * HKV + (ll)h * KVD;
    const float4* row4  = (const float4*)(S + eoff);
    uint2*        row16 = (uint2*)(S16 + eoff);

    // issue the row load FIRST (latency hides under the stats fold below)
    float4 v = make_float4(0.f, 0.f, 0.f, 0.f);
    if (tid < 240) v = row4[tid];

    // stats for this (br, b, h) from scores-GEMM tile partials (warp 0 only)
    __shared__ float smu, srs;
    if (wid == 0) {
        const int brOff[4]  = {1792, 1536, 1024, 0};
        const int tilesZ[4] = {8, 8, 16, 32};          // 8 * myt
        const int base = brOff[br] + (b * NH + h) * tilesZ[br];
        float s = 0.f, s2 = 0.f;
        for (int i = lane; i < tilesZ[br]; i += 32) {
            s  += part[(base + i) * 2 + 0];
            s2 += part[(base + i) * 2 + 1];
        }
#pragma unroll
        for (int o = 16; o > 0; o >>= 1) {
            s  += __shfl_xor_sync(0xffffffffu, s,  o);
            s2 += __shfl_xor_sync(0xffffffffu, s2, o);
        }
        if (lane == 0) {
            const float cnt = (float)C * (float)KVD;
            const float m = s / cnt;
            smu = m;
            srs = rsqrtf(s2 / cnt - m * m + 1e-5f) * 1.4426950408889634f;  // fold log2(e)
        }
    }
    __syncthreads();
    const float m = smu;
    const float r = srs;

    float4 e;
    float lsum = 0.f;
    if (tid < 240) {
        e.x = exp2f((v.x - m) * r);
        e.y = exp2f((v.y - m) * r);
        e.z = exp2f((v.z - m) * r);
        e.w = exp2f((v.w - m) * r);
        lsum = (e.x + e.y) + (e.z + e.w);
    }

    // warp shuffle reduce, then one cross-warp pass
    __shared__ float red[8];
#pragma unroll
    for (int o = 16; o > 0; o >>= 1)
        lsum += __shfl_xor_sync(0xffffffffu, lsum, o);
    if (lane == 0) red[wid] = lsum;
    __syncthreads();
    const float tot = ((red[0] + red[1]) + (red[2] + red[3]))
                    + ((red[4] + red[5]) + (red[6] + red[7]));
    const float inv = 1.f / tot;

    if (tid < 240) {
        uint2 o16;
        o16.x = h2pack(e.x * inv, e.y * inv);
        o16.y = h2pack(e.z * inv, e.w * inv);
        row16[tid] = o16;
    }
}

// ---------------- host launch ------------------------------------------------------------
extern "C" void kernel_launch(void* const* d_in, const int* in_sizes, int n_in,
                              void* d_out, int out_size)
{
    const float* emb[4]  = {(const float*)d_in[0], (const float*)d_in[1],
                            (const float*)d_in[2], (const float*)d_in[3]};
    const float* emb_all = (const float*)d_in[4];
    const float* Wq[4]   = {(const float*)d_in[5], (const float*)d_in[6],
                            (const float*)d_in[7], (const float*)d_in[8]};
    const float* Wk      = (const float*)d_in[9];
    const float* Wv      = (const float*)d_in[10];
    const float* Wo[4]   = {(const float*)d_in[11], (const float*)d_in[12],
                            (const float*)d_in[13], (const float*)d_in[14]};
    float* out = (float*)d_out;

    float *Sp, *partp;
    __half *Gp, *Tp, *S16p, *Up, *CXp;
    cudaGetSymbolAddress((void**)&Gp,    g_G);
    cudaGetSymbolAddress((void**)&Tp,    g_T);
    cudaGetSymbolAddress((void**)&Sp,    g_S);
    cudaGetSymbolAddress((void**)&S16p,  g_S16);
    cudaGetSymbolAddress((void**)&Up,    g_U);
    cudaGetSymbolAddress((void**)&CXp,   g_CX);
    cudaGetSymbolAddress((void**)&partp, g_part);

    const float rscale = 1.f / sqrtf(960.f);

    float* Sb[4];
    float* Ob[4];
    __half *Gb[4], *Tb[4], *S16b[4], *Ub[4], *CXb[4];
    int Cb_[4], myt_[4];
    for (int br = 0; br < 4; br++) {
        const int Cb = BR_C(br), P = BR_P(br);
        Cb_[br] = Cb;
        myt_[br] = (Cb + 127) / 128;
        Gb[br]   = Gp   + (ll)BATCH * P * KVD;
        Tb[br]   = Tp   + (ll)BATCH * NH * P * KVD;
        Sb[br]   = Sp   + (ll)BATCH * P * HKV;
        S16b[br] = S16p + (ll)BATCH * P * HKV;
        Ub[br]   = Up   + (ll)BATCH * NH * P * KVD;
        CXb[br]  = CXp  + (ll)BATCH * P * NTOK;
        Ob[br]   = out  + (ll)BATCH * NTOK * P;
    }

    auto fill = [](GemmDesc& g, const void* A, const void* B, void* C,
                   int M, int N, int K, int lda, int ldb, int ldc,
                   int aDiv, ll aS1, ll aS2, int bDiv, ll bS1, ll bS2,
                   int cDiv, ll cS1, ll cS2, float alpha,
                   int xB, int yB, int zB, int& cum) {
        g.A = (const float*)A; g.B = (const float*)B; g.C = (float*)C;
        g.M = M; g.N = N; g.K = K; g.lda = lda; g.ldb = ldb; g.ldc = ldc;
        g.aDiv = aDiv; g.aS1 = aS1; g.aS2 = aS2;
        g.bDiv = bDiv; g.bS1 = bS1; g.bS2 = bS2;
        g.cDiv = cDiv; g.cS1 = cS1; g.cS2 = cS2;
        g.alpha = alpha; g.xB = xB; g.yB = yB; g.off = cum;
        cum += xB * yB * zB;
    };

    Desc4 dG, dT, dS, dU, dCX, dO;
    dG.part = dT.part = dU.part = dCX.part = dO.part = nullptr;
    dS.part = partp;
    int nG = 0, nT = 0, nS = 0, nU = 0, nCX = 0, nO = 0;
    // heavy-branch-first: slot s holds branch 3-s
    for (int slot = 0; slot < 4; slot++) {
        const int br = 3 - slot;
        const int Cb = Cb_[br], myt = myt_[br];

        // G[b][c][j] = sum_n emb[b][n][c] * emb_all[b][n][j]      -> fp16 C
        fill(dG.d[slot], emb[br], emb_all, Gb[br],
             Cb, KVD, NTOK, Cb, KVD, KVD,
             1, (ll)NTOK * Cb, 0,  1, (ll)NTOK * KVD, 0,
             1, (ll)Cb * KVD, 0, 1.f, 8, myt, BATCH, nG);

        // T[b,h][c][j] = sum_d Wq[h][c][d] * G16[b][d][j]          -> fp16 B, fp16 C
        fill(dT.d[slot], Wq[br], Gb[br], Tb[br],
             Cb, KVD, Cb, Cb, KVD, KVD,
             NH, 0, (ll)Cb * Cb,  NH, (ll)Cb * KVD, 0,
             1, (ll)Cb * KVD, 0, 1.f, 8, myt, BATCH * NH, nT);

        // scores[b,h][c][o] = sum_k T16[b,h][c][k] * Wk[h][o][k]   -> fp16 A, fp32 C + stats
        fill(dS.d[slot], Tb[br], Wk, Sb[br],
             Cb, KVD, KVD, KVD, KVD, HKV,
             1, (ll)Cb * KVD, 0,  NH, 0, (ll)KVD * KVD,
             NH, (ll)Cb * HKV, KVD, rscale, 8, myt, BATCH * NH, nS);

        // U[b,h][c][k] = 0.25 * sum_o probs16[b][c][h*960+o] * Wv[h][o][k]
        // per-head split-K: z = b*NH+h, K=960, 2048 uniform blocks -> 98.8% wave util
        fill(dU.d[slot], S16b[br], Wv, Ub[br],
             Cb, KVD, KVD, HKV, KVD, KVD,
             NH, (ll)Cb * HKV, KVD,  NH, 0, (ll)KVD * KVD,
             1, (ll)Cb * KVD, 0, 0.25f, 8, myt, BATCH * NH, nU);

        // ctx[b][c][n] = sum_k (sum_h U16[b,h][c][k]) * emb_all[b][n][k]  -> A4 sum, fp16 C
        fill(dCX.d[slot], Ub[br], emb_all, CXb[br],
             Cb, NTOK, KVD, KVD, KVD, NTOK,
             1, (ll)NH * Cb * KVD, 0,  1, (ll)NTOK * KVD, 0,
             1, (ll)Cb * NTOK, 0, 1.f, NTOK / 128, myt, BATCH, nCX);

        // O[b][n][j] = sum_c ctx16[b][c][n] * Wo[j][c]             -> fp16 A (T), fp32 C
        fill(dO.d[slot], CXb[br], Wo[br], Ob[br],
             NTOK, Cb, Cb, NTOK, Cb, Cb,
             1, (ll)Cb * NTOK, 0,  1, 0, 0,
             1, (ll)NTOK * Cb, 0, 1.f, myt, NTOK / 128, BATCH, nO);
    }

    // 7 launches, single stream        TA     TB     STATS  AH     BH     CH     A4
    tgemm_m<true,  true,  false, false, false, true,  false><<<nG,  256>>>(dG);
    tgemm_m<false, true,  false, false, true,  true,  false><<<nT,  256>>>(dT);
    tgemm_m<false, false, true,  true,  false, false, false><<<nS,  256>>>(dS);
    norm_softmax_m<<<30720, 256>>>(Sp, S16p, partp);
    tgemm_m<false, true,  false, true,  false, true,  false><<<nU,  256>>>(dU);
    tgemm_m<false, false, false, true,  false, true,  true ><<<nCX, 256>>>(dCX);
    tgemm_m<true,  false, false, true,  false, false, false><<<nO,  256>>>(dO);

    (void)in_sizes; (void)n_in; (void)out_size;
}

// round 15
// speedup vs baseline: 1.0527x; 1.0527x over previous
#include <cuda_runtime.h>
#include <cuda_fp16.h>
#include <cstdint>
#include <math.h>

#define BATCH 8
#define NTOK  1024
#define KVD   960
#define NH    4
#define HKV   (NH * KVD)   // 3840
#define CT    960          // sum of branch channels 64+128+256+512

typedef long long ll;

#define BR_C(br)   (64 << (br))
#define BR_P(br)   ((64 << (br)) - 64)

// ---------------- scratch (static __device__ — no allocations allowed) ----------------
static __device__ __half g_G  [(size_t)BATCH * CT * KVD];
static __device__ __half g_T  [(size_t)BATCH * NH * CT * KVD];
static __device__ float  g_S  [(size_t)BATCH * CT * HKV];      // fp32 scores
static __device__ __half g_S16[(size_t)BATCH * CT * HKV];      // fp16 probs
static __device__ __half g_Us [(size_t)BATCH * CT * KVD];
static __device__ __half g_CX [(size_t)BATCH * CT * NTOK];
static __device__ float  g_part[2048 * 2];

// ---------------- fp16 helpers ----------------
__device__ __forceinline__ uint32_t h2pack(float lo, float hi) {
    uint32_t r;
    asm("cvt.rn.f16x2.f32 %0, %1, %2;" : "=r"(r) : "f"(hi), "f"(lo));
    return r;
}
__device__ __forceinline__ uint32_t packh(__half lo, __half hi) {
    __half2 h = __halves2half2(lo, hi);
    return *(uint32_t*)&h;
}

__device__ __forceinline__ void mma16816(float* c, const uint4& a, const uint2& b) {
    asm volatile(
        "mma.sync.aligned.m16n8k16.row.col.f32.f16.f16.f32 "
        "{%0,%1,%2,%3}, {%4,%5,%6,%7}, {%8,%9}, {%0,%1,%2,%3};"
        : "+f"(c[0]), "+f"(c[1]), "+f"(c[2]), "+f"(c[3])
        : "r"(a.x), "r"(a.y), "r"(a.z), "r"(a.w), "r"(b.x), "r"(b.y));
}

// ======================= fp32 producers =======================
template <bool T>
__device__ __forceinline__ void ldgA(const float* __restrict__ A, int lda, int tileM,
                                     int M, int kt, int t, float4* q)
{
    const int b = t >> 4, kb = b >> 3, mb = b & 7;
    const int m0 = tileM + mb * 16 + ((t & 15) >> 1);
    const int k0 = kt + kb * 16 + (t & 1) * 4;
    const bool v0 = m0 < M, v1 = (m0 + 8) < M;
    if (!T) {
        const float4 Z = make_float4(0.f, 0.f, 0.f, 0.f);
        q[0] = v0 ? *(const float4*)(A + (ll)m0 * lda + k0)           : Z;
        q[1] = v0 ? *(const float4*)(A + (ll)m0 * lda + k0 + 8)       : Z;
        q[2] = v1 ? *(const float4*)(A + (ll)(m0 + 8) * lda + k0)     : Z;
        q[3] = v1 ? *(const float4*)(A + (ll)(m0 + 8) * lda + k0 + 8) : Z;
    } else {
        float* f = (float*)q;
#pragma unroll
        for (int run = 0; run < 2; run++)
#pragma unroll
            for (int i = 0; i < 4; i++) {
                const ll ko = (ll)(k0 + run * 8 + i) * lda;
                f[run * 4 + i]     = v0 ? A[ko + m0]     : 0.f;
                f[8 + run * 4 + i] = v1 ? A[ko + m0 + 8] : 0.f;
            }
    }
}

__device__ __forceinline__ void stsA(uint4* sA, int t, const float4* q)
{
    uint4 v0, v1;
    v0.x = h2pack(q[0].x, q[0].y); v0.y = h2pack(q[2].x, q[2].y);
    v0.z = h2pack(q[1].x, q[1].y); v0.w = h2pack(q[3].x, q[3].y);
    v1.x = h2pack(q[0].z, q[0].w); v1.y = h2pack(q[2].z, q[2].w);
    v1.z = h2pack(q[1].z, q[1].w); v1.w = h2pack(q[3].z, q[3].w);
    const int b = t >> 4;
    const int l0 = (t & 15) * 2, l1 = l0 + 1;
    sA[b * 32 + (l0 ^ ((l0 >> 3) & 1))] = v0;
    sA[b * 32 + (l1 ^ ((l1 >> 3) & 1))] = v1;
}

template <bool T>
__device__ __forceinline__ void ldgB(const float* __restrict__ B, int ldb, int tileN,
                                     int N, int kt, int t, float4* q)
{
    const int b = t >> 3, kb = b >> 4, nb = b & 15;
    const int n = tileN + nb * 8 + (t & 7);
    const int k0 = kt + kb * 16;
    const bool v = n < N;
    if (!T) {
        const float4 Z = make_float4(0.f, 0.f, 0.f, 0.f);
        const float4* p = (const float4*)(B + (ll)n * ldb + k0);
        q[0] = v ? p[0] : Z; q[1] = v ? p[1] : Z;
        q[2] = v ? p[2] : Z; q[3] = v ? p[3] : Z;
    } else {
        float* f = (float*)q;
#pragma unroll
        for (int i = 0; i < 16; i++)
            f[i] = v ? B[(ll)(k0 + i) * ldb + n] : 0.f;
    }
}

__device__ __forceinline__ void stsB(uint4* sB, int t, const float4* q)
{
    uint4 v0, v1;
    v0.x = h2pack(q[0].x, q[0].y); v0.y = h2pack(q[2].x, q[2].y);
    v0.z = h2pack(q[0].z, q[0].w); v0.w = h2pack(q[2].z, q[2].w);
    v1.x = h2pack(q[1].x, q[1].y); v1.y = h2pack(q[3].x, q[3].y);
    v1.z = h2pack(q[1].z, q[1].w); v1.w = h2pack(q[3].z, q[3].w);
    const int b = t >> 3;
    const int u0 = (t & 7) * 2, u1 = u0 + 1;
    sB[b * 16 + (u0 ^ ((u0 >> 3) & 1))] = v0;
    sB[b * 16 + (u1 ^ ((u1 >> 3) & 1))] = v1;
}

// ======================= fp16 producers (pure repack) =======================
__device__ __forceinline__ void ldgA16(const __half* __restrict__ A, int lda, int tileM,
                                       int M, int kt, int t, uint2* w)
{
    const int b = t >> 4, kb = b >> 3, mb = b & 7;
    const int m0 = tileM + mb * 16 + ((t & 15) >> 1);
    const int k0 = kt + kb * 16 + (t & 1) * 4;
    const bool v0 = m0 < M, v1 = (m0 + 8) < M;
    const uint2 Z = make_uint2(0u, 0u);
    w[0] = v0 ? *(const uint2*)(A + (ll)m0 * lda + k0)           : Z;
    w[1] = v0 ? *(const uint2*)(A + (ll)m0 * lda + k0 + 8)       : Z;
    w[2] = v1 ? *(const uint2*)(A + (ll)(m0 + 8) * lda + k0)     : Z;
    w[3] = v1 ? *(const uint2*)(A + (ll)(m0 + 8) * lda + k0 + 8) : Z;
}

__device__ __forceinline__ void ldgA16T(const __half* __restrict__ A, int lda, int tileM,
                                        int M, int kt, int t, uint2* w)
{
    const int b = t >> 4, kb = b >> 3, mb = b & 7;
    const int m0 = tileM + mb * 16 + ((t & 15) >> 1);
    const int k0 = kt + kb * 16 + (t & 1) * 4;
    const bool v0 = m0 < M, v1 = (m0 + 8) < M;
    const __half Z = __float2half(0.f);
    __half h0[8], h1[8];
#pragma unroll
    for (int run = 0; run < 2; run++)
#pragma unroll
        for (int i = 0; i < 4; i++) {
            const ll ko = (ll)(k0 + run * 8 + i) * lda;
            h0[run * 4 + i] = v0 ? A[ko + m0]     : Z;
            h1[run * 4 + i] = v1 ? A[ko + m0 + 8] : Z;
        }
    w[0] = make_uint2(packh(h0[0], h0[1]), packh(h0[2], h0[3]));
    w[1] = make_uint2(packh(h0[4], h0[5]), packh(h0[6], h0[7]));
    w[2] = make_uint2(packh(h1[0], h1[1]), packh(h1[2], h1[3]));
    w[3] = make_uint2(packh(h1[4], h1[5]), packh(h1[6], h1[7]));
}

__device__ __forceinline__ void stsA16(uint4* sA, int t, const uint2* w)
{
    uint4 v0, v1;
    v0.x = w[0].x; v0.y = w[2].x; v0.z = w[1].x; v0.w = w[3].x;
    v1.x = w[0].y; v1.y = w[2].y; v1.z = w[1].y; v1.w = w[3].y;
    const int b = t >> 4;
    const int l0 = (t & 15) * 2, l1 = l0 + 1;
    sA[b * 32 + (l0 ^ ((l0 >> 3) & 1))] = v0;
    sA[b * 32 + (l1 ^ ((l1 >> 3) & 1))] = v1;
}

__device__ __forceinline__ void ldgB16T(const __half* __restrict__ B, int ldb, int tileN,
                                        int N, int kt, int t, uint4& v0, uint4& v1)
{
    const int b = t >> 3, kb = b >> 4, nb = b & 15;
    const int n = tileN + nb * 8 + (t & 7);
    const int k0 = kt + kb * 16;
    const bool v = n < N;
    const __half Z = __float2half(0.f);
    __half f[16];
#pragma unroll
    for (int i = 0; i < 16; i++)
        f[i] = v ? B[(ll)(k0 + i) * ldb + n] : Z;
    v0.x = packh(f[0],  f[1]);  v0.y = packh(f[8],  f[9]);
    v0.z = packh(f[2],  f[3]);  v0.w = packh(f[10], f[11]);
    v1.x = packh(f[4],  f[5]);  v1.y = packh(f[12], f[13]);
    v1.z = packh(f[6],  f[7]);  v1.w = packh(f[14], f[15]);
}

__device__ __forceinline__ void stsB16(uint4* sB, int t, const uint4& v0, const uint4& v1)
{
    const int b = t >> 3;
    const int u0 = (t & 7) * 2, u1 = u0 + 1;
    sB[b * 16 + (u0 ^ ((u0 >> 3) & 1))] = v0;
    sB[b * 16 + (u1 ^ ((u1 >> 3) & 1))] = v1;
}

// ======================= merged-stage GEMM descriptors =======================
struct GemmDesc {
    const float* A;
    const float* B;
    float*       C;
    int M, N, K, lda, ldb, ldc;
    int aDiv, bDiv, cDiv;
    ll aS1, aS2, bS1, bS2, cS1, cS2;
    float alpha;
    int xB, yB;
    int off;
};
struct Desc4 { GemmDesc d[4]; float* part; };

// ---------------- config-templated compute path ----------------
template <int JMAX>
__device__ __forceinline__ void compute_T(const uint4* __restrict__ ap,
                                          const uint2* __restrict__ bp,
                                          float acc[2][8][4],
                                          int wmSel, int nbBase, int la, int lb2)
{
#pragma unroll
    for (int s = 0; s < 2; s++) {
        uint4 av[2];
#pragma unroll
        for (int i = 0; i < 2; i++)
            av[i] = ap[(s * 8 + wmSel * 2 + i) * 32 + la];
        uint2 bv[JMAX];
#pragma unroll
        for (int j = 0; j < JMAX; j++)
            bv[j] = bp[(s * 16 + nbBase + j) * 32 + lb2];
#pragma unroll
        for (int i = 0; i < 2; i++)
#pragma unroll
            for (int j = 0; j < JMAX; j++)
                mma16816(acc[i][j], av[i], bv[j]);
    }
}

// ======================= fp16 tensor-core merged batched GEMM =======================
// Runtime half-tile modes: mHalf (M==64) and nHalf (N - tileN <= 64) skip padded HMMAs.
template <bool TA, bool TB, bool STATS, bool AH, bool BH, bool CH>
__global__ __launch_bounds__(256, 2)
void tgemm_m(Desc4 ds)
{
    __shared__ uint4 sA[2][512];
    __shared__ uint4 sB[2][512];

    const int bid = blockIdx.x;
    int br = 0;
    if (bid >= ds.d[1].off) br = 1;
    if (bid >= ds.d[2].off) br = 2;
    if (bid >= ds.d[3].off) br = 3;
    const GemmDesc& g = ds.d[br];

    const int local = bid - g.off;
    const int x  = local % g.xB;
    const int t2 = local / g.xB;
    const int y  = t2 % g.yB;
    const int z  = t2 / g.yB;

    const ll aOff = (ll)(z / g.aDiv) * g.aS1 + (ll)(z % g.aDiv) * g.aS2;
    const ll bOff = (ll)(z / g.bDiv) * g.bS1 + (ll)(z % g.bDiv) * g.bS2;
    const ll cOff = (ll)(z / g.cDiv) * g.cS1 + (ll)(z % g.cDiv) * g.cS2;
    const float*  A   = g.A + aOff;
    const __half* A16 = (const __half*)g.A + aOff;
    const float*  B   = g.B + bOff;
    const __half* B16 = (const __half*)g.B + bOff;
    float*        C   = g.C + cOff;
    __half*       C16 = (__half*)g.C + cOff;
    const int M = g.M, N = g.N, K = g.K;
    const int lda = g.lda, ldb = g.ldb, ldc = g.ldc;
    const float alpha = g.alpha;

    const int tid  = threadIdx.x;
    const int lane = tid & 31;
    const int wid  = tid >> 5;
    const int tileM = y * 128;
    const int tileN = x * 128;

    const bool mHalf = (M == 64);
    const bool nHalf = (N - tileN) <= 64;
    const int wmSel = mHalf ? (wid >> 2) : (wid >> 1);
    const int wnSel = mHalf ? (wid & 3)  : (wid & 1);
    const int nbBase = (mHalf ? wnSel * 4 : wnSel * 8) >> (nHalf ? 1 : 0);
    const int jmax = (mHalf ? 4 : 8) >> (nHalf ? 1 : 0);
    const int cfg = (mHalf ? 2 : 0) | (nHalf ? 1 : 0);

    float acc[2][8][4];
#pragma unroll
    for (int i = 0; i < 2; i++)
#pragma unroll
        for (int j = 0; j < 8; j++)
#pragma unroll
            for (int t = 0; t < 4; t++) acc[i][j][t] = 0.f;

    const int la  = lane ^ ((lane >> 3) & 1);
    const int lb2 = (((lane >> 1) ^ ((lane >> 4) & 1)) << 1) | (lane & 1);

    auto compute = [&](int buf) {
        const uint4* ap = sA[buf];
        const uint2* bp = (const uint2*)sB[buf];
        switch (cfg) {
            case 0: compute_T<8>(ap, bp, acc, wmSel, nbBase, la, lb2); break;
            case 1: compute_T<4>(ap, bp, acc, wmSel, nbBase, la, lb2); break;
            case 2: compute_T<4>(ap, bp, acc, wmSel, nbBase, la, lb2); break;
            default: compute_T<2>(ap, bp, acc, wmSel, nbBase, la, lb2); break;
        }
    };

    const int nk = K >> 5;
    float4 qa[4], qb[4];
    uint2  wa[4];
    uint4  wb0, wb1;

    auto produceA = [&](int kt) {
        if (AH) { if (TA) ldgA16T(A16, lda, tileM, M, kt, tid, wa);
                  else    ldgA16 (A16, lda, tileM, M, kt, tid, wa); }
        else      ldgA<TA>(A, lda, tileM, M, kt, tid, qa);
    };
    auto produceB = [&](int kt) {
        if (BH) ldgB16T(B16, ldb, tileN, N, kt, tid, wb0, wb1);
        else    ldgB<TB>(B, ldb, tileN, N, kt, tid, qb);
    };
    auto storeAB = [&](int buf) {
        if (AH) stsA16(sA[buf], tid, wa); else stsA(sA[buf], tid, qa);
        if (BH) stsB16(sB[buf], tid, wb0, wb1); else stsB(sB[buf], tid, qb);
    };

    produceA(0);
    produceB(0);
    storeAB(0);
    __syncthreads();

    int buf = 0;
    for (int it = 1; it < nk; it++) {
        produceA(it * 32);
        produceB(it * 32);
        compute(buf);
        storeAB(buf ^ 1);
        __syncthreads();
        buf ^= 1;
    }
    compute(buf);

    if (STATS) {
        float s = 0.f, s2 = 0.f;
#pragma unroll
        for (int i = 0; i < 2; i++)
            for (int j = 0; j < jmax; j++)
#pragma unroll
                for (int t = 0; t < 4; t++) {
                    const float v = acc[i][j][t] * alpha;
                    s += v; s2 += v * v;
                }
        __syncthreads();
        float* sa = (float*)&sA[0][0];
        float* sb = sa + 256;
        sa[tid] = s; sb[tid] = s2;
        __syncthreads();
        for (int off = 128; off > 0; off >>= 1) {
            if (tid < off) { sa[tid] += sa[tid + off]; sb[tid] += sb[tid + off]; }
            __syncthreads();
        }
        if (tid == 0) {
            ds.part[bid * 2 + 0] = sa[0];
            ds.part[bid * 2 + 1] = sb[0];
        }
    }

    // epilogue (generalized over configs)
    for (int i = 0; i < 2; i++) {
        for (int j = 0; j < jmax; j++) {
            const int row = tileM + wmSel * 32 + i * 16 + (lane >> 2);
            const int col = tileN + nbBase * 8 + j * 8 + ((lane & 3) << 1);
            if (col < N) {
                if (CH) {
                    if (row < M)
                        *(uint32_t*)&C16[(ll)row * ldc + col] =
                            h2pack(acc[i][j][0] * alpha, acc[i][j][1] * alpha);
                    if (row + 8 < M)
                        *(uint32_t*)&C16[(ll)(row + 8) * ldc + col] =
                            h2pack(acc[i][j][2] * alpha, acc[i][j][3] * alpha);
                } else {
                    if (row < M) {
                        float2 v = make_float2(acc[i][j][0] * alpha, acc[i][j][1] * alpha);
                        *(float2*)&C[(ll)row * ldc + col] = v;
                    }
                    if (row + 8 < M) {
                        float2 v = make_float2(acc[i][j][2] * alpha, acc[i][j][3] * alpha);
                        *(float2*)&C[(ll)(row + 8) * ldc + col] = v;
                    }
                }
            }
        }
    }
}

// ---------------- fused stats-fold + norm + softmax: fp32 scores -> fp16 probs ------------
// dS fill order is br3,br2,br1,br0: per-branch partial offsets {br0:1792, br1:1536, br2:1024, br3:0}
__global__ __launch_bounds__(256) void norm_softmax_m(
    const float* __restrict__ S, __half* __restrict__ S16,
    const float* __restrict__ part)
{
    const int gid = blockIdx.x;
    int br = 0;
    if (gid >= 2048)  br = 1;
    if (gid >= 6144)  br = 2;
    if (gid >= 14336) br = 3;
    const int off = (2048 << br) - 2048;
    const int local = gid - off;
    const int C = BR_C(br);

    const int h = local % NH;
    const int bc = local / NH;
    const int c = bc % C;
    const int b = bc / C;
    const int tid  = threadIdx.x;
    const int lane = tid & 31;
    const int wid  = tid >> 5;

    const ll eoff = (ll)BATCH * BR_P(br) * HKV + ((ll)b * C + c) * HKV + (ll)h * KVD;
    const float4* row4  = (const float4*)(S + eoff);
    uint2*        row16 = (uint2*)(S16 + eoff);

    // issue the row load FIRST (latency hides under the stats fold below)
    float4 v = make_float4(0.f, 0.f, 0.f, 0.f);
    if (tid < 240) v = row4[tid];

    // stats for this (br, b, h) from scores-GEMM tile partials (warp 0 only)
    __shared__ float smu, srs;
    if (wid == 0) {
        const int brOff[4]  = {1792, 1536, 1024, 0};
        const int tilesZ[4] = {8, 8, 16, 32};          // 8 * myt
        const int base = brOff[br] + (b * NH + h) * tilesZ[br];
        float s = 0.f, s2 = 0.f;
        for (int i = lane; i < tilesZ[br]; i += 32) {
            s  += part[(base + i) * 2 + 0];
            s2 += part[(base + i) * 2 + 1];
        }
#pragma unroll
        for (int o = 16; o > 0; o >>= 1) {
            s  += __shfl_xor_sync(0xffffffffu, s,  o);
            s2 += __shfl_xor_sync(0xffffffffu, s2, o);
        }
        if (lane == 0) {
            const float cnt = (float)C * (float)KVD;
            const float m = s / cnt;
            smu = m;
            srs = rsqrtf(s2 / cnt - m * m + 1e-5f) * 1.4426950408889634f;  // fold log2(e)
        }
    }
    __syncthreads();
    const float m = smu;
    const float r = srs;

    float4 e;
    float lsum = 0.f;
    if (tid < 240) {
        e.x = exp2f((v.x - m) * r);
        e.y = exp2f((v.y - m) * r);
        e.z = exp2f((v.z - m) * r);
        e.w = exp2f((v.w - m) * r);
        lsum = (e.x + e.y) + (e.z + e.w);
    }

    // warp shuffle reduce, then one cross-warp pass (2 barriers total in kernel)
    __shared__ float red[8];
#pragma unroll
    for (int o = 16; o > 0; o >>= 1)
        lsum += __shfl_xor_sync(0xffffffffu, lsum, o);
    if (lane == 0) red[wid] = lsum;
    __syncthreads();
    const float tot = ((red[0] + red[1]) + (red[2] + red[3]))
                    + ((red[4] + red[5]) + (red[6] + red[7]));
    const float inv = 1.f / tot;

    if (tid < 240) {
        uint2 o16;
        o16.x = h2pack(e.x * inv, e.y * inv);
        o16.y = h2pack(e.z * inv, e.w * inv);
        row16[tid] = o16;
    }
}

// ---------------- host launch ------------------------------------------------------------
extern "C" void kernel_launch(void* const* d_in, const int* in_sizes, int n_in,
                              void* d_out, int out_size)
{
    const float* emb[4]  = {(const float*)d_in[0], (const float*)d_in[1],
                            (const float*)d_in[2], (const float*)d_in[3]};
    const float* emb_all = (const float*)d_in[4];
    const float* Wq[4]   = {(const float*)d_in[5], (const float*)d_in[6],
                            (const float*)d_in[7], (const float*)d_in[8]};
    const float* Wk      = (const float*)d_in[9];
    const float* Wv      = (const float*)d_in[10];
    const float* Wo[4]   = {(const float*)d_in[11], (const float*)d_in[12],
                            (const float*)d_in[13], (const float*)d_in[14]};
    float* out = (float*)d_out;

    float *Sp, *partp;
    __half *Gp, *Tp, *S16p, *Usp, *CXp;
    cudaGetSymbolAddress((void**)&Gp,    g_G);
    cudaGetSymbolAddress((void**)&Tp,    g_T);
    cudaGetSymbolAddress((void**)&Sp,    g_S);
    cudaGetSymbolAddress((void**)&S16p,  g_S16);
    cudaGetSymbolAddress((void**)&Usp,   g_Us);
    cudaGetSymbolAddress((void**)&CXp,   g_CX);
    cudaGetSymbolAddress((void**)&partp, g_part);

    const float rscale = 1.f / sqrtf(960.f);

    float* Sb[4];
    float* Ob[4];
    __half *Gb[4], *Tb[4], *S16b[4], *Usb[4], *CXb[4];
    int Cb_[4], myt_[4];
    for (int br = 0; br < 4; br++) {
        const int Cb = BR_C(br), P = BR_P(br);
        Cb_[br] = Cb;
        myt_[br] = (Cb + 127) / 128;
        Gb[br]   = Gp   + (ll)BATCH * P * KVD;
        Tb[br]   = Tp   + (ll)BATCH * NH * P * KVD;
        Sb[br]   = Sp   + (ll)BATCH * P * HKV;
        S16b[br] = S16p + (ll)BATCH * P * HKV;
        Usb[br]  = Usp  + (ll)BATCH * P * KVD;
        CXb[br]  = CXp  + (ll)BATCH * P * NTOK;
        Ob[br]   = out  + (ll)BATCH * NTOK * P;
    }

    auto fill = [](GemmDesc& g, const void* A, const void* B, void* C,
                   int M, int N, int K, int lda, int ldb, int ldc,
                   int aDiv, ll aS1, ll aS2, int bDiv, ll bS1, ll bS2,
                   int cDiv, ll cS1, ll cS2, float alpha,
                   int xB, int yB, int zB, int& cum) {
        g.A = (const float*)A; g.B = (const float*)B; g.C = (float*)C;
        g.M = M; g.N = N; g.K = K; g.lda = lda; g.ldb = ldb; g.ldc = ldc;
        g.aDiv = aDiv; g.aS1 = aS1; g.aS2 = aS2;
        g.bDiv = bDiv; g.bS1 = bS1; g.bS2 = bS2;
        g.cDiv = cDiv; g.cS1 = cS1; g.cS2 = cS2;
        g.alpha = alpha; g.xB = xB; g.yB = yB; g.off = cum;
        cum += xB * yB * zB;
    };

    Desc4 dG, dT, dS, dU, dCX, dO;
    dG.part = dT.part = dU.part = dCX.part = dO.part = nullptr;
    dS.part = partp;
    int nG = 0, nT = 0, nS = 0, nU = 0, nCX = 0, nO = 0;
    // heavy-branch-first: slot s holds branch 3-s
    for (int slot = 0; slot < 4; slot++) {
        const int br = 3 - slot;
        const int Cb = Cb_[br], myt = myt_[br];

        // G[b][c][j] = sum_n emb[b][n][c] * emb_all[b][n][j]      -> fp16 C
        fill(dG.d[slot], emb[br], emb_all, Gb[br],
             Cb, KVD, NTOK, Cb, KVD, KVD,
             1, (ll)NTOK * Cb, 0,  1, (ll)NTOK * KVD, 0,
             1, (ll)Cb * KVD, 0, 1.f, 8, myt, BATCH, nG);

        // T[b,h][c][j] = sum_d Wq[h][c][d] * G16[b][d][j]          -> fp16 B, fp16 C
        fill(dT.d[slot], Wq[br], Gb[br], Tb[br],
             Cb, KVD, Cb, Cb, KVD, KVD,
             NH, 0, (ll)Cb * Cb,  NH, (ll)Cb * KVD, 0,
             1, (ll)Cb * KVD, 0, 1.f, 8, myt, BATCH * NH, nT);

        // scores[b,h][c][o] = sum_k T16[b,h][c][k] * Wk[h][o][k]   -> fp16 A, fp32 C + stats
        fill(dS.d[slot], Tb[br], Wk, Sb[br],
             Cb, KVD, KVD, KVD, KVD, HKV,
             1, (ll)Cb * KVD, 0,  NH, 0, (ll)KVD * KVD,
             NH, (ll)Cb * HKV, KVD, rscale, 8, myt, BATCH * NH, nS);

        // Us[b][c][k] = 0.25 * sum_{ho} probs16[b][c][ho] * Wv[ho][k]  -> fp16 A, fp16 C
        fill(dU.d[slot], S16b[br], Wv, Usb[br],
             Cb, KVD, HKV, HKV, KVD, KVD,
             1, (ll)Cb * HKV, 0,  1, 0, 0,
             1, (ll)Cb * KVD, 0, 0.25f, 8, myt, BATCH, nU);

        // ctx[b][c][n] = sum_k Us16[b][c][k] * emb_all[b][n][k]    -> fp16 A, fp16 C
        fill(dCX.d[slot], Usb[br], emb_all, CXb[br],
             Cb, NTOK, KVD, KVD, KVD, NTOK,
             1, (ll)Cb * KVD, 0,  1, (ll)NTOK * KVD, 0,
             1, (ll)Cb * NTOK, 0, 1.f, NTOK / 128, myt, BATCH, nCX);

        // O[b][n][j] = sum_c ctx16[b][c][n] * Wo[j][c]             -> fp16 A (T), fp32 C
        fill(dO.d[slot], CXb[br], Wo[br], Ob[br],
             NTOK, Cb, Cb, NTOK, Cb, Cb,
             1, (ll)Cb * NTOK, 0,  1, 0, 0,
             1, (ll)NTOK * Cb, 0, 1.f, myt, NTOK / 128, BATCH, nO);
    }

    // 7 launches, single stream        TA     TB     STATS  AH     BH     CH
    tgemm_m<true,  true,  false, false, false, true ><<<nG,  256>>>(dG);
    tgemm_m<false, true,  false, false, true,  true ><<<nT,  256>>>(dT);
    tgemm_m<false, false, true,  true,  false, false><<<nS,  256>>>(dS);
    norm_softmax_m<<<30720, 256>>>(Sp, S16p, partp);
    tgemm_m<false, true,  false, true,  false, true ><<<nU,  256>>>(dU);
    tgemm_m<false, false, false, true,  false, true ><<<nCX, 256>>>(dCX);
    tgemm_m<true,  false, false, true,  false, false><<<nO,  256>>>(dO);

    (void)in_sizes; (void)n_in; (void)out_size;
}